// round 3
// baseline (speedup 1.0000x reference)
#include <cuda_runtime.h>
#include <math.h>

#define T_TOK 4096   // B*S
#define HDIM  2048
#define NEXP  8
#define DDIM  2048

#define BM 128
#define BN 64
#define BK 8

// ---- scratch (static device globals: no runtime allocation) ----
__device__ int   g_cnt[NEXP];
__device__ int   g_tok[NEXP * T_TOK];    // token*2 + slot
__device__ float g_gate[NEXP * T_TOK];
__device__ float g_y[(size_t)T_TOK * 2 * DDIM];   // per-(token,slot) expert output, 67MB

__global__ void zero_cnt_kernel() {
    if (threadIdx.x < NEXP) g_cnt[threadIdx.x] = 0;
}

__device__ __forceinline__ float gelu_tanh(float v) {
    // jax.nn.gelu default (approximate=True)
    float v3 = v * v * v;
    return 0.5f * v * (1.0f + tanhf(0.7978845608028654f * (v + 0.044715f * v3)));
}

// One block per token: logits -> softmax -> top2 -> renorm -> append to lists
__global__ void router_kernel(const float* __restrict__ x,
                              const float* __restrict__ rw,
                              const float* __restrict__ rb) {
    int t = blockIdx.x;
    const float* xr = x + (size_t)t * HDIM;

    float acc[NEXP];
#pragma unroll
    for (int e = 0; e < NEXP; e++) acc[e] = 0.f;

    for (int h = threadIdx.x; h < HDIM; h += blockDim.x) {
        float xv = xr[h];
        const float* r = rw + (size_t)h * NEXP;
#pragma unroll
        for (int e = 0; e < NEXP; e++) acc[e] += xv * r[e];
    }

    __shared__ float red[256][NEXP + 1];
#pragma unroll
    for (int e = 0; e < NEXP; e++) red[threadIdx.x][e] = acc[e];
    __syncthreads();
    for (int s = 128; s > 0; s >>= 1) {
        if (threadIdx.x < s) {
#pragma unroll
            for (int e = 0; e < NEXP; e++)
                red[threadIdx.x][e] += red[threadIdx.x + s][e];
        }
        __syncthreads();
    }

    if (threadIdx.x == 0) {
        float lg[NEXP];
        float mx = -1e30f;
#pragma unroll
        for (int e = 0; e < NEXP; e++) {
            lg[e] = red[0][e] + rb[e];
            mx = fmaxf(mx, lg[e]);
        }
        // exp (un-normalized probs: ordering & top2-renorm identical to softmax)
#pragma unroll
        for (int e = 0; e < NEXP; e++) lg[e] = expf(lg[e] - mx);

        int i0 = 0;
#pragma unroll
        for (int e = 1; e < NEXP; e++) if (lg[e] > lg[i0]) i0 = e;
        int i1 = (i0 == 0) ? 1 : 0;
#pragma unroll
        for (int e = 0; e < NEXP; e++) if (e != i0 && lg[e] > lg[i1]) i1 = e;

        float p0 = lg[i0], p1 = lg[i1];
        float inv = 1.f / (p0 + p1);

        int pos0 = atomicAdd(&g_cnt[i0], 1);
        g_tok[i0 * T_TOK + pos0]  = t * 2 + 0;
        g_gate[i0 * T_TOK + pos0] = p0 * inv;
        int pos1 = atomicAdd(&g_cnt[i1], 1);
        g_tok[i1 * T_TOK + pos1]  = t * 2 + 1;
        g_gate[i1 * T_TOK + pos1] = p1 * inv;
    }
}

// Grouped expert GEMM: Y[tokslot, n] = gelu(x[tok] @ W_e[:, n] + b_e[n]) * gate
__global__ __launch_bounds__(256)
void expert_gemm_kernel(const float* __restrict__ x,
                        const float* __restrict__ ew,
                        const float* __restrict__ eb) {
    int e = blockIdx.z;
    int cnt = g_cnt[e];
    int m0 = blockIdx.y * BM;
    if (m0 >= cnt) return;
    int n0 = blockIdx.x * BN;
    const float* w  = ew + (size_t)e * HDIM * DDIM;
    const float* be = eb + (size_t)e * DDIM;

    __shared__ float As[BK][BM];
    __shared__ float Bs[BK][BN];

    int tid = threadIdx.x;
    // A-tile load map: 128 rows, 2 threads/row (float4 each over k)
    int am = tid >> 1;
    int ak = (tid & 1) * 4;
    int gm = m0 + am;
    const float* arow = nullptr;
    if (gm < cnt) {
        int ts = g_tok[e * T_TOK + gm];
        arow = x + (size_t)(ts >> 1) * HDIM;
    }
    // B-tile load map (threads 0..127): 8 k-rows x 16 float4
    int bk = tid >> 4;
    int bn = (tid & 15) * 4;

    int row = (tid >> 4) * 8;
    int col = (tid & 15) * 4;

    float c[8][4];
#pragma unroll
    for (int i = 0; i < 8; i++)
#pragma unroll
        for (int j = 0; j < 4; j++) c[i][j] = 0.f;

    for (int k0 = 0; k0 < HDIM; k0 += BK) {
        float4 av = make_float4(0.f, 0.f, 0.f, 0.f);
        if (arow) av = *reinterpret_cast<const float4*>(arow + k0 + ak);
        As[ak + 0][am] = av.x;
        As[ak + 1][am] = av.y;
        As[ak + 2][am] = av.z;
        As[ak + 3][am] = av.w;
        if (tid < 128) {
            float4 bv = *reinterpret_cast<const float4*>(
                w + (size_t)(k0 + bk) * DDIM + n0 + bn);
            *reinterpret_cast<float4*>(&Bs[bk][bn]) = bv;
        }
        __syncthreads();
#pragma unroll
        for (int kk = 0; kk < BK; kk++) {
            float4 a0 = *reinterpret_cast<const float4*>(&As[kk][row]);
            float4 a1 = *reinterpret_cast<const float4*>(&As[kk][row + 4]);
            float4 b  = *reinterpret_cast<const float4*>(&Bs[kk][col]);
            float av8[8] = {a0.x, a0.y, a0.z, a0.w, a1.x, a1.y, a1.z, a1.w};
            float bv4[4] = {b.x, b.y, b.z, b.w};
#pragma unroll
            for (int i = 0; i < 8; i++)
#pragma unroll
                for (int j = 0; j < 4; j++)
                    c[i][j] = fmaf(av8[i], bv4[j], c[i][j]);
        }
        __syncthreads();
    }

#pragma unroll
    for (int i = 0; i < 8; i++) {
        int gm2 = m0 + row + i;
        if (gm2 < cnt) {
            int ts = g_tok[e * T_TOK + gm2];
            float gate = g_gate[e * T_TOK + gm2];
            float4 o;
            o.x = gelu_tanh(c[i][0] + be[n0 + col + 0]) * gate;
            o.y = gelu_tanh(c[i][1] + be[n0 + col + 1]) * gate;
            o.z = gelu_tanh(c[i][2] + be[n0 + col + 2]) * gate;
            o.w = gelu_tanh(c[i][3] + be[n0 + col + 3]) * gate;
            *reinterpret_cast<float4*>(g_y + (size_t)ts * DDIM + n0 + col) = o;
        }
    }
}

// Output projection: out[t, f] = (y[t,0,:] + y[t,1,:]) @ out_w + out_b
__global__ __launch_bounds__(256)
void out_gemm_kernel(const float* __restrict__ ow,
                     const float* __restrict__ ob,
                     float* __restrict__ out) {
    int m0 = blockIdx.y * BM;
    int n0 = blockIdx.x * BN;

    __shared__ float As[BK][BM];
    __shared__ float Bs[BK][BN];

    int tid = threadIdx.x;
    int am = tid >> 1;
    int ak = (tid & 1) * 4;
    const float* y0 = g_y + (size_t)(m0 + am) * 2 * DDIM;
    int bk = tid >> 4;
    int bn = (tid & 15) * 4;

    int row = (tid >> 4) * 8;
    int col = (tid & 15) * 4;

    float c[8][4];
#pragma unroll
    for (int i = 0; i < 8; i++)
#pragma unroll
        for (int j = 0; j < 4; j++) c[i][j] = 0.f;

    for (int k0 = 0; k0 < DDIM; k0 += BK) {
        float4 a0 = *reinterpret_cast<const float4*>(y0 + k0 + ak);
        float4 a1 = *reinterpret_cast<const float4*>(y0 + DDIM + k0 + ak);
        As[ak + 0][am] = a0.x + a1.x;
        As[ak + 1][am] = a0.y + a1.y;
        As[ak + 2][am] = a0.z + a1.z;
        As[ak + 3][am] = a0.w + a1.w;
        if (tid < 128) {
            float4 bv = *reinterpret_cast<const float4*>(
                ow + (size_t)(k0 + bk) * DDIM + n0 + bn);
            *reinterpret_cast<float4*>(&Bs[bk][bn]) = bv;
        }
        __syncthreads();
#pragma unroll
        for (int kk = 0; kk < BK; kk++) {
            float4 a0r = *reinterpret_cast<const float4*>(&As[kk][row]);
            float4 a1r = *reinterpret_cast<const float4*>(&As[kk][row + 4]);
            float4 b   = *reinterpret_cast<const float4*>(&Bs[kk][col]);
            float av8[8] = {a0r.x, a0r.y, a0r.z, a0r.w, a1r.x, a1r.y, a1r.z, a1r.w};
            float bv4[4] = {b.x, b.y, b.z, b.w};
#pragma unroll
            for (int i = 0; i < 8; i++)
#pragma unroll
                for (int j = 0; j < 4; j++)
                    c[i][j] = fmaf(av8[i], bv4[j], c[i][j]);
        }
        __syncthreads();
    }

#pragma unroll
    for (int i = 0; i < 8; i++) {
        int t = m0 + row + i;
        float4 o;
        o.x = c[i][0] + ob[n0 + col + 0];
        o.y = c[i][1] + ob[n0 + col + 1];
        o.z = c[i][2] + ob[n0 + col + 2];
        o.w = c[i][3] + ob[n0 + col + 3];
        *reinterpret_cast<float4*>(out + (size_t)t * DDIM + n0 + col) = o;
    }
}

extern "C" void kernel_launch(void* const* d_in, const int* in_sizes, int n_in,
                              void* d_out, int out_size) {
    const float* x  = (const float*)d_in[0];
    const float* rw = (const float*)d_in[1];
    const float* rb = (const float*)d_in[2];
    const float* ew = (const float*)d_in[3];
    const float* eb = (const float*)d_in[4];
    const float* ow = (const float*)d_in[5];
    const float* ob = (const float*)d_in[6];
    float* out = (float*)d_out;

    zero_cnt_kernel<<<1, 32>>>();
    router_kernel<<<T_TOK, 256>>>(x, rw, rb);
    dim3 g1(DDIM / BN, T_TOK / BM, NEXP);
    expert_gemm_kernel<<<g1, 256>>>(x, ew, eb);
    dim3 g2(DDIM / BN, T_TOK / BM);
    out_gemm_kernel<<<g2, 256>>>(ow, ob, out);
}

// round 4
// speedup vs baseline: 2.2673x; 2.2673x over previous
#include <cuda_runtime.h>
#include <math.h>

#define T_TOK 4096   // B*S
#define HDIM  2048
#define NEXP  8
#define DDIM  2048

#define BM 128
#define BN 128
#define BK 16
#define ASTR 20     // BK + 4 pad: fragment-read conflict-free
#define BSTR 136    // BN + 8 pad: stride % 32 == 8 -> conflict-free

// ---- scratch (static device globals: no runtime allocation) ----
__device__ int   g_cnt[NEXP];
__device__ int   g_tok[NEXP * T_TOK];    // token*2 + slot
__device__ float g_gate[NEXP * T_TOK];
__device__ float g_y[(size_t)T_TOK * 2 * DDIM];   // per-(token,slot) expert output

__global__ void zero_cnt_kernel() {
    if (threadIdx.x < NEXP) g_cnt[threadIdx.x] = 0;
}

__device__ __forceinline__ float gelu_tanh(float v) {
    float v3 = v * v * v;
    return 0.5f * v * (1.0f + tanhf(0.7978845608028654f * (v + 0.044715f * v3)));
}

// fp32 -> tf32 with round-to-nearest (unbiased; truncation would bias ~1e-3)
__device__ __forceinline__ unsigned f2tf(float f) {
    unsigned u;
    asm("cvt.rna.tf32.f32 %0, %1;" : "=r"(u) : "f"(f));
    return u;
}

__device__ __forceinline__ void mma_tf32(float* c, const unsigned* a, const unsigned* b) {
    asm volatile(
        "mma.sync.aligned.m16n8k8.row.col.f32.tf32.tf32.f32 "
        "{%0,%1,%2,%3}, {%4,%5,%6,%7}, {%8,%9}, {%0,%1,%2,%3};"
        : "+f"(c[0]), "+f"(c[1]), "+f"(c[2]), "+f"(c[3])
        : "r"(a[0]), "r"(a[1]), "r"(a[2]), "r"(a[3]), "r"(b[0]), "r"(b[1]));
}

// One k-stage (BK=16 = two k8 chunks) of warp-tile 64x32 mma work.
__device__ __forceinline__ void compute_stage(
    const unsigned (*__restrict__ As)[ASTR],
    const unsigned (*__restrict__ Bs)[BSTR],
    float c[4][4][4], int wm, int wn, int lq, int tg)
{
#pragma unroll
    for (int kc = 0; kc < BK; kc += 8) {
        unsigned af[4][4];
        unsigned bf[4][2];
#pragma unroll
        for (int mt = 0; mt < 4; mt++) {
            int r = wm * 64 + mt * 16 + lq;
            af[mt][0] = As[r][kc + tg];
            af[mt][1] = As[r + 8][kc + tg];
            af[mt][2] = As[r][kc + tg + 4];
            af[mt][3] = As[r + 8][kc + tg + 4];
        }
#pragma unroll
        for (int nt = 0; nt < 4; nt++) {
            int nn = wn * 32 + nt * 8 + lq;
            bf[nt][0] = Bs[kc + tg][nn];
            bf[nt][1] = Bs[kc + tg + 4][nn];
        }
#pragma unroll
        for (int mt = 0; mt < 4; mt++)
#pragma unroll
            for (int nt = 0; nt < 4; nt++)
                mma_tf32(c[mt][nt], af[mt], bf[nt]);
    }
}

// One block per token: logits -> softmax -> top2 -> renorm -> append to lists
__global__ void router_kernel(const float* __restrict__ x,
                              const float* __restrict__ rw,
                              const float* __restrict__ rb) {
    int t = blockIdx.x;
    const float* xr = x + (size_t)t * HDIM;

    float acc[NEXP];
#pragma unroll
    for (int e = 0; e < NEXP; e++) acc[e] = 0.f;

    for (int h = threadIdx.x; h < HDIM; h += blockDim.x) {
        float xv = xr[h];
        const float* r = rw + (size_t)h * NEXP;
#pragma unroll
        for (int e = 0; e < NEXP; e++) acc[e] += xv * r[e];
    }

    __shared__ float red[256][NEXP + 1];
#pragma unroll
    for (int e = 0; e < NEXP; e++) red[threadIdx.x][e] = acc[e];
    __syncthreads();
    for (int s = 128; s > 0; s >>= 1) {
        if (threadIdx.x < s) {
#pragma unroll
            for (int e = 0; e < NEXP; e++)
                red[threadIdx.x][e] += red[threadIdx.x + s][e];
        }
        __syncthreads();
    }

    if (threadIdx.x == 0) {
        float lg[NEXP];
        float mx = -1e30f;
#pragma unroll
        for (int e = 0; e < NEXP; e++) {
            lg[e] = red[0][e] + rb[e];
            mx = fmaxf(mx, lg[e]);
        }
#pragma unroll
        for (int e = 0; e < NEXP; e++) lg[e] = expf(lg[e] - mx);

        int i0 = 0;
#pragma unroll
        for (int e = 1; e < NEXP; e++) if (lg[e] > lg[i0]) i0 = e;
        int i1 = (i0 == 0) ? 1 : 0;
#pragma unroll
        for (int e = 0; e < NEXP; e++) if (e != i0 && lg[e] > lg[i1]) i1 = e;

        float p0 = lg[i0], p1 = lg[i1];
        float inv = 1.f / (p0 + p1);

        int pos0 = atomicAdd(&g_cnt[i0], 1);
        g_tok[i0 * T_TOK + pos0]  = t * 2 + 0;
        g_gate[i0 * T_TOK + pos0] = p0 * inv;
        int pos1 = atomicAdd(&g_cnt[i1], 1);
        g_tok[i1 * T_TOK + pos1]  = t * 2 + 1;
        g_gate[i1 * T_TOK + pos1] = p1 * inv;
    }
}

// Grouped expert GEMM (tf32 tensor): Y[ts, n] = gelu(x[tok] @ W_e + b_e) * gate
__global__ __launch_bounds__(256, 1)
void expert_gemm_tf32(const float* __restrict__ x,
                      const float* __restrict__ ew,
                      const float* __restrict__ eb) {
    int e = blockIdx.z;
    int cnt = g_cnt[e];
    int m0 = blockIdx.y * BM;
    if (m0 >= cnt) return;
    int n0 = blockIdx.x * BN;
    const float* w = ew + (size_t)e * HDIM * DDIM;

    __shared__ __align__(16) unsigned As[2][BM][ASTR];
    __shared__ __align__(16) unsigned Bs[2][BK][BSTR];

    int tid = threadIdx.x;
    int lane = tid & 31;
    int wid  = tid >> 5;
    int wm = wid >> 2, wn = wid & 3;
    int lq = lane >> 2, tg = lane & 3;

    // A staging: thread handles rows mA0, mA1 (float4 over k)
    int mA0 = tid >> 2;
    int mA1 = mA0 + 64;
    int kqA = (tid & 3) * 4;
    const float* arow0;
    const float* arow1;
    {
        int gm0 = m0 + mA0;
        int gm1 = m0 + mA1;
        int t0 = (gm0 < cnt) ? (g_tok[e * T_TOK + gm0] >> 1) : 0;  // dummy row 0 if OOB
        int t1 = (gm1 < cnt) ? (g_tok[e * T_TOK + gm1] >> 1) : 0;
        arow0 = x + (size_t)t0 * HDIM + kqA;
        arow1 = x + (size_t)t1 * HDIM + kqA;
    }
    // B staging: thread handles k-rows kB0, kB1 at columns nB..nB+3
    int kB0 = tid >> 5;
    int kB1 = kB0 + 8;
    int nB  = (tid & 31) * 4;
    const float* brow = w + n0 + nB;

    float c[4][4][4];
#pragma unroll
    for (int i = 0; i < 4; i++)
#pragma unroll
        for (int j = 0; j < 4; j++)
#pragma unroll
            for (int q = 0; q < 4; q++) c[i][j][q] = 0.f;

    float4 ra0 = *(const float4*)(arow0);
    float4 ra1 = *(const float4*)(arow1);
    float4 rb0 = *(const float4*)(brow + (size_t)kB0 * DDIM);
    float4 rb1 = *(const float4*)(brow + (size_t)kB1 * DDIM);

#define STORE_STAGE(sb)                                                                        \
    do {                                                                                       \
        *(uint4*)&As[sb][mA0][kqA] = make_uint4(f2tf(ra0.x), f2tf(ra0.y), f2tf(ra0.z), f2tf(ra0.w)); \
        *(uint4*)&As[sb][mA1][kqA] = make_uint4(f2tf(ra1.x), f2tf(ra1.y), f2tf(ra1.z), f2tf(ra1.w)); \
        *(uint4*)&Bs[sb][kB0][nB]  = make_uint4(f2tf(rb0.x), f2tf(rb0.y), f2tf(rb0.z), f2tf(rb0.w)); \
        *(uint4*)&Bs[sb][kB1][nB]  = make_uint4(f2tf(rb1.x), f2tf(rb1.y), f2tf(rb1.z), f2tf(rb1.w)); \
    } while (0)

    STORE_STAGE(0);
    __syncthreads();

#pragma unroll 1
    for (int i = 1; i < HDIM / BK; i++) {
        int k0 = i * BK;
        ra0 = *(const float4*)(arow0 + k0);
        ra1 = *(const float4*)(arow1 + k0);
        rb0 = *(const float4*)(brow + (size_t)(k0 + kB0) * DDIM);
        rb1 = *(const float4*)(brow + (size_t)(k0 + kB1) * DDIM);
        int cb = (i - 1) & 1;
        compute_stage(As[cb], Bs[cb], c, wm, wn, lq, tg);
        STORE_STAGE(cb ^ 1);
        __syncthreads();
    }
    compute_stage(As[(HDIM / BK - 1) & 1], Bs[(HDIM / BK - 1) & 1], c, wm, wn, lq, tg);

    // epilogue: bias + gelu + gate, scatter to g_y
    const float* be = eb + (size_t)e * DDIM;
#pragma unroll
    for (int mt = 0; mt < 4; mt++) {
        int rlo = wm * 64 + mt * 16 + lq;
        int rhi = rlo + 8;
        int glo = m0 + rlo, ghi = m0 + rhi;
        bool oklo = glo < cnt, okhi = ghi < cnt;
        int tslo = 0, tshi = 0;
        float gtlo = 0.f, gthi = 0.f;
        if (oklo) { tslo = g_tok[e * T_TOK + glo]; gtlo = g_gate[e * T_TOK + glo]; }
        if (okhi) { tshi = g_tok[e * T_TOK + ghi]; gthi = g_gate[e * T_TOK + ghi]; }
#pragma unroll
        for (int nt = 0; nt < 4; nt++) {
            int col = n0 + wn * 32 + nt * 8 + 2 * tg;
            float b0 = be[col], b1 = be[col + 1];
            if (oklo) {
                float2 o;
                o.x = gelu_tanh(c[mt][nt][0] + b0) * gtlo;
                o.y = gelu_tanh(c[mt][nt][1] + b1) * gtlo;
                *(float2*)(g_y + (size_t)tslo * DDIM + col) = o;
            }
            if (okhi) {
                float2 o;
                o.x = gelu_tanh(c[mt][nt][2] + b0) * gthi;
                o.y = gelu_tanh(c[mt][nt][3] + b1) * gthi;
                *(float2*)(g_y + (size_t)tshi * DDIM + col) = o;
            }
        }
    }
#undef STORE_STAGE
}

// Output projection (tf32 tensor): out[t] = (y[t,0] + y[t,1]) @ out_w + out_b
__global__ __launch_bounds__(256, 1)
void out_gemm_tf32(const float* __restrict__ ow,
                   const float* __restrict__ ob,
                   float* __restrict__ out) {
    int m0 = blockIdx.y * BM;
    int n0 = blockIdx.x * BN;

    __shared__ __align__(16) unsigned As[2][BM][ASTR];
    __shared__ __align__(16) unsigned Bs[2][BK][BSTR];

    int tid = threadIdx.x;
    int lane = tid & 31;
    int wid  = tid >> 5;
    int wm = wid >> 2, wn = wid & 3;
    int lq = lane >> 2, tg = lane & 3;

    int mA0 = tid >> 2;
    int mA1 = mA0 + 64;
    int kqA = (tid & 3) * 4;
    const float* ya0 = g_y + (size_t)(2 * (m0 + mA0)) * DDIM + kqA;  // slot0; slot1 at +DDIM
    const float* ya1 = g_y + (size_t)(2 * (m0 + mA1)) * DDIM + kqA;

    int kB0 = tid >> 5;
    int kB1 = kB0 + 8;
    int nB  = (tid & 31) * 4;
    const float* brow = ow + n0 + nB;

    float c[4][4][4];
#pragma unroll
    for (int i = 0; i < 4; i++)
#pragma unroll
        for (int j = 0; j < 4; j++)
#pragma unroll
            for (int q = 0; q < 4; q++) c[i][j][q] = 0.f;

    float4 ra0, ra1, rb0, rb1;
    {
        float4 u = *(const float4*)(ya0);
        float4 v = *(const float4*)(ya0 + DDIM);
        ra0 = make_float4(u.x + v.x, u.y + v.y, u.z + v.z, u.w + v.w);
        u = *(const float4*)(ya1);
        v = *(const float4*)(ya1 + DDIM);
        ra1 = make_float4(u.x + v.x, u.y + v.y, u.z + v.z, u.w + v.w);
        rb0 = *(const float4*)(brow + (size_t)kB0 * DDIM);
        rb1 = *(const float4*)(brow + (size_t)kB1 * DDIM);
    }

#define STORE_STAGE(sb)                                                                        \
    do {                                                                                       \
        *(uint4*)&As[sb][mA0][kqA] = make_uint4(f2tf(ra0.x), f2tf(ra0.y), f2tf(ra0.z), f2tf(ra0.w)); \
        *(uint4*)&As[sb][mA1][kqA] = make_uint4(f2tf(ra1.x), f2tf(ra1.y), f2tf(ra1.z), f2tf(ra1.w)); \
        *(uint4*)&Bs[sb][kB0][nB]  = make_uint4(f2tf(rb0.x), f2tf(rb0.y), f2tf(rb0.z), f2tf(rb0.w)); \
        *(uint4*)&Bs[sb][kB1][nB]  = make_uint4(f2tf(rb1.x), f2tf(rb1.y), f2tf(rb1.z), f2tf(rb1.w)); \
    } while (0)

    STORE_STAGE(0);
    __syncthreads();

#pragma unroll 1
    for (int i = 1; i < DDIM / BK; i++) {
        int k0 = i * BK;
        float4 u = *(const float4*)(ya0 + k0);
        float4 v = *(const float4*)(ya0 + DDIM + k0);
        ra0 = make_float4(u.x + v.x, u.y + v.y, u.z + v.z, u.w + v.w);
        u = *(const float4*)(ya1 + k0);
        v = *(const float4*)(ya1 + DDIM + k0);
        ra1 = make_float4(u.x + v.x, u.y + v.y, u.z + v.z, u.w + v.w);
        rb0 = *(const float4*)(brow + (size_t)(k0 + kB0) * DDIM);
        rb1 = *(const float4*)(brow + (size_t)(k0 + kB1) * DDIM);
        int cb = (i - 1) & 1;
        compute_stage(As[cb], Bs[cb], c, wm, wn, lq, tg);
        STORE_STAGE(cb ^ 1);
        __syncthreads();
    }
    compute_stage(As[(DDIM / BK - 1) & 1], Bs[(DDIM / BK - 1) & 1], c, wm, wn, lq, tg);

#pragma unroll
    for (int mt = 0; mt < 4; mt++) {
        int rlo = m0 + wm * 64 + mt * 16 + lq;
        int rhi = rlo + 8;
#pragma unroll
        for (int nt = 0; nt < 4; nt++) {
            int col = n0 + wn * 32 + nt * 8 + 2 * tg;
            float b0 = ob[col], b1 = ob[col + 1];
            float2 o;
            o.x = c[mt][nt][0] + b0;
            o.y = c[mt][nt][1] + b1;
            *(float2*)(out + (size_t)rlo * DDIM + col) = o;
            o.x = c[mt][nt][2] + b0;
            o.y = c[mt][nt][3] + b1;
            *(float2*)(out + (size_t)rhi * DDIM + col) = o;
        }
    }
#undef STORE_STAGE
}

extern "C" void kernel_launch(void* const* d_in, const int* in_sizes, int n_in,
                              void* d_out, int out_size) {
    const float* x  = (const float*)d_in[0];
    const float* rw = (const float*)d_in[1];
    const float* rb = (const float*)d_in[2];
    const float* ew = (const float*)d_in[3];
    const float* eb = (const float*)d_in[4];
    const float* ow = (const float*)d_in[5];
    const float* ob = (const float*)d_in[6];
    float* out = (float*)d_out;

    zero_cnt_kernel<<<1, 32>>>();
    router_kernel<<<T_TOK, 256>>>(x, rw, rb);
    dim3 g1(DDIM / BN, T_TOK / BM, NEXP);
    expert_gemm_tf32<<<g1, 256>>>(x, ew, eb);
    dim3 g2(DDIM / BN, T_TOK / BM);
    out_gemm_tf32<<<g2, 256>>>(ow, ob, out);
}

// round 9
// speedup vs baseline: 2.9333x; 1.2937x over previous
#include <cuda_runtime.h>
#include <math.h>

#define T_TOK 4096   // B*S
#define HDIM  2048
#define NEXP  8
#define DDIM  2048

#define BM 128
#define BN 128
#define BK 16
#define ASTR 20     // BK + 4 pad: conflict-free fragment reads
#define BSTR 136    // BN + 8 pad: stride % 32 == 8 -> conflict-free
#define NSTAGE 4

#define A_STAGE_BYTES (BM * ASTR * 4)                       // 10240
#define B_STAGE_BYTES (BK * BSTR * 4)                       // 8704
#define SMEM_BYTES (NSTAGE * (A_STAGE_BYTES + B_STAGE_BYTES))  // 75776

// ---- scratch (static device globals: no runtime allocation) ----
__device__ int   g_cnt[NEXP];
__device__ int   g_tok[NEXP * T_TOK];    // token*2 + slot
__device__ float g_gate[NEXP * T_TOK];
__device__ float g_y[(size_t)T_TOK * 2 * DDIM];    // per-(token,slot) expert output (raw fp32)
__device__ float g_c[(size_t)T_TOK * DDIM];        // combined y0+y1, tf32-rounded
__device__ float g_xr[(size_t)T_TOK * HDIM];       // tf32-rounded x
__device__ float g_ewr[(size_t)NEXP * HDIM * DDIM];// tf32-rounded expert_w (128MB)
__device__ float g_owr[(size_t)DDIM * DDIM];       // tf32-rounded out_w

__global__ void zero_cnt_kernel() {
    if (threadIdx.x < NEXP) g_cnt[threadIdx.x] = 0;
}

__device__ __forceinline__ float gelu_tanh(float v) {
    float v3 = v * v * v;
    return 0.5f * v * (1.0f + tanhf(0.7978845608028654f * (v + 0.044715f * v3)));
}

// fp32 -> tf32 round-to-nearest, returned as fp32 value (low mantissa bits zero)
__device__ __forceinline__ float tf32r(float f) {
    unsigned u;
    asm("cvt.rna.tf32.f32 %0, %1;" : "=r"(u) : "f"(f));
    return __uint_as_float(u);
}

__device__ __forceinline__ void mma_tf32(float* c, const unsigned* a, const unsigned* b) {
    asm volatile(
        "mma.sync.aligned.m16n8k8.row.col.f32.tf32.tf32.f32 "
        "{%0,%1,%2,%3}, {%4,%5,%6,%7}, {%8,%9}, {%0,%1,%2,%3};"
        : "+f"(c[0]), "+f"(c[1]), "+f"(c[2]), "+f"(c[3])
        : "r"(a[0]), "r"(a[1]), "r"(a[2]), "r"(a[3]), "r"(b[0]), "r"(b[1]));
}

__device__ __forceinline__ void cp16(unsigned dst, const void* src, int sz) {
    asm volatile("cp.async.cg.shared.global [%0], [%1], 16, %2;\n"
                 :: "r"(dst), "l"(src), "r"(sz));
}
__device__ __forceinline__ void cp_commit() {
    asm volatile("cp.async.commit_group;\n" ::: "memory");
}
__device__ __forceinline__ void cp_wait2() {
    asm volatile("cp.async.wait_group 2;\n" ::: "memory");
}

// One k-stage (BK=16 = two k8 chunks) of warp-tile 64x32 mma work.
__device__ __forceinline__ void compute_stage(
    const unsigned (*__restrict__ As)[ASTR],
    const unsigned (*__restrict__ Bs)[BSTR],
    float c[4][4][4], int wm, int wn, int lq, int tg)
{
#pragma unroll
    for (int kc = 0; kc < BK; kc += 8) {
        unsigned af[4][4];
        unsigned bf[4][2];
#pragma unroll
        for (int mt = 0; mt < 4; mt++) {
            int r = wm * 64 + mt * 16 + lq;
            af[mt][0] = As[r][kc + tg];
            af[mt][1] = As[r + 8][kc + tg];
            af[mt][2] = As[r][kc + tg + 4];
            af[mt][3] = As[r + 8][kc + tg + 4];
        }
#pragma unroll
        for (int nt = 0; nt < 4; nt++) {
            int nn = wn * 32 + nt * 8 + lq;
            bf[nt][0] = Bs[kc + tg][nn];
            bf[nt][1] = Bs[kc + tg + 4][nn];
        }
#pragma unroll
        for (int mt = 0; mt < 4; mt++)
#pragma unroll
            for (int nt = 0; nt < 4; nt++)
                mma_tf32(c[mt][nt], af[mt], bf[nt]);
    }
}

// Pre-round a tensor to tf32 (vectorized)
__global__ void preround_kernel(const float* __restrict__ src,
                                float* __restrict__ dst, int n4) {
    int i = blockIdx.x * blockDim.x + threadIdx.x;
    if (i < n4) {
        float4 v = ((const float4*)src)[i];
        v.x = tf32r(v.x); v.y = tf32r(v.y); v.z = tf32r(v.z); v.w = tf32r(v.w);
        ((float4*)dst)[i] = v;
    }
}

// One block per token: logits -> softmax -> top2 -> renorm -> append to lists.
// Also writes g_xr = tf32-rounded x (fused: x is already being read).
__global__ void router_kernel(const float* __restrict__ x,
                              const float* __restrict__ rw,
                              const float* __restrict__ rb) {
    int t = blockIdx.x;
    const float* xr = x + (size_t)t * HDIM;
    float* xo = g_xr + (size_t)t * HDIM;

    float acc[NEXP];
#pragma unroll
    for (int e = 0; e < NEXP; e++) acc[e] = 0.f;

    for (int h = threadIdx.x; h < HDIM; h += blockDim.x) {
        float xv = xr[h];
        xo[h] = tf32r(xv);
        const float* r = rw + (size_t)h * NEXP;
#pragma unroll
        for (int e = 0; e < NEXP; e++) acc[e] += xv * r[e];
    }

    __shared__ float red[256][NEXP + 1];
#pragma unroll
    for (int e = 0; e < NEXP; e++) red[threadIdx.x][e] = acc[e];
    __syncthreads();
    for (int s = 128; s > 0; s >>= 1) {
        if (threadIdx.x < s) {
#pragma unroll
            for (int e = 0; e < NEXP; e++)
                red[threadIdx.x][e] += red[threadIdx.x + s][e];
        }
        __syncthreads();
    }

    if (threadIdx.x == 0) {
        float lg[NEXP];
        float mx = -1e30f;
#pragma unroll
        for (int e = 0; e < NEXP; e++) {
            lg[e] = red[0][e] + rb[e];
            mx = fmaxf(mx, lg[e]);
        }
#pragma unroll
        for (int e = 0; e < NEXP; e++) lg[e] = expf(lg[e] - mx);

        int i0 = 0;
#pragma unroll
        for (int e = 1; e < NEXP; e++) if (lg[e] > lg[i0]) i0 = e;
        int i1 = (i0 == 0) ? 1 : 0;
#pragma unroll
        for (int e = 0; e < NEXP; e++) if (e != i0 && lg[e] > lg[i1]) i1 = e;

        float p0 = lg[i0], p1 = lg[i1];
        float inv = 1.f / (p0 + p1);

        int pos0 = atomicAdd(&g_cnt[i0], 1);
        g_tok[i0 * T_TOK + pos0]  = t * 2 + 0;
        g_gate[i0 * T_TOK + pos0] = p0 * inv;
        int pos1 = atomicAdd(&g_cnt[i1], 1);
        g_tok[i1 * T_TOK + pos1]  = t * 2 + 1;
        g_gate[i1 * T_TOK + pos1] = p1 * inv;
    }
}

// Grouped expert GEMM (tf32 tensor, cp.async 4-stage):
// Y[ts, n] = gelu(x[tok] @ W_e + b_e) * gate   (raw fp32 into g_y)
__global__ __launch_bounds__(256, 2)
void expert_gemm_tf32(const float* __restrict__ eb) {
    extern __shared__ char smem[];
    unsigned sbase;
    asm("{ .reg .u64 t; cvta.to.shared.u64 t, %1; cvt.u32.u64 %0, t; }"
        : "=r"(sbase) : "l"(smem));

    int e = blockIdx.z;
    int cnt = g_cnt[e];
    int m0 = blockIdx.y * BM;
    if (m0 >= cnt) return;
    int n0 = blockIdx.x * BN;
    const float* w = g_ewr + (size_t)e * HDIM * DDIM;

    int tid = threadIdx.x;
    int lane = tid & 31;
    int wid  = tid >> 5;
    int wm = wid >> 2, wn = wid & 3;
    int lq = lane >> 2, tg = lane & 3;

    // A copy map: 2 threads/row, 2x16B each
    int mA = tid >> 1;
    int kqA = (tid & 1) * 8;
    const float* asrc;
    int asz;
    {
        int gm = m0 + mA;
        if (gm < cnt) {
            asrc = g_xr + (size_t)(g_tok[e * T_TOK + gm] >> 1) * HDIM + kqA;
            asz = 16;
        } else { asrc = g_xr; asz = 0; }
    }
    unsigned adst = sbase + (mA * ASTR + kqA) * 4;
    // B copy map: 16 threads/k-row, 2x16B each
    int kB = tid >> 4;
    int nB = (tid & 15) * 8;
    const float* bsrc = w + (size_t)kB * DDIM + n0 + nB;
    unsigned bdst = sbase + NSTAGE * A_STAGE_BYTES + (kB * BSTR + nB) * 4;

#define ISSUE(st, k0)                                                             \
    do {                                                                          \
        cp16(adst + (st) * A_STAGE_BYTES,      asrc + (k0),          asz);        \
        cp16(adst + (st) * A_STAGE_BYTES + 16, asrc + (k0) + 4,      asz);        \
        cp16(bdst + (st) * B_STAGE_BYTES,      bsrc + (size_t)(k0) * DDIM,     16); \
        cp16(bdst + (st) * B_STAGE_BYTES + 16, bsrc + (size_t)(k0) * DDIM + 4, 16); \
        cp_commit();                                                              \
    } while (0)

    float c[4][4][4];
#pragma unroll
    for (int i = 0; i < 4; i++)
#pragma unroll
        for (int j = 0; j < 4; j++)
#pragma unroll
            for (int q = 0; q < 4; q++) c[i][j][q] = 0.f;

    ISSUE(0, 0); ISSUE(1, BK); ISSUE(2, 2 * BK);

    const int NK = HDIM / BK;
#pragma unroll 1
    for (int i = 0; i < NK; i++) {
        cp_wait2();
        __syncthreads();
        int st = i & 3;
        compute_stage((const unsigned (*)[ASTR])(smem + st * A_STAGE_BYTES),
                      (const unsigned (*)[BSTR])(smem + NSTAGE * A_STAGE_BYTES + st * B_STAGE_BYTES),
                      c, wm, wn, lq, tg);
        int nx = i + NSTAGE - 1;
        if (nx < NK) { ISSUE(nx & 3, nx * BK); }
        else         { cp_commit(); }
    }
#undef ISSUE

    // epilogue: bias + gelu + gate, scatter to g_y (raw fp32)
    const float* be = eb + (size_t)e * DDIM;
#pragma unroll
    for (int mt = 0; mt < 4; mt++) {
        int rlo = wm * 64 + mt * 16 + lq;
        int rhi = rlo + 8;
        int glo = m0 + rlo, ghi = m0 + rhi;
        bool oklo = glo < cnt, okhi = ghi < cnt;
        int tslo = 0, tshi = 0;
        float gtlo = 0.f, gthi = 0.f;
        if (oklo) { tslo = g_tok[e * T_TOK + glo]; gtlo = g_gate[e * T_TOK + glo]; }
        if (okhi) { tshi = g_tok[e * T_TOK + ghi]; gthi = g_gate[e * T_TOK + ghi]; }
#pragma unroll
        for (int nt = 0; nt < 4; nt++) {
            int col = n0 + wn * 32 + nt * 8 + 2 * tg;
            float b0 = be[col], b1 = be[col + 1];
            if (oklo) {
                float2 o;
                o.x = gelu_tanh(c[mt][nt][0] + b0) * gtlo;
                o.y = gelu_tanh(c[mt][nt][1] + b1) * gtlo;
                *(float2*)(g_y + (size_t)tslo * DDIM + col) = o;
            }
            if (okhi) {
                float2 o;
                o.x = gelu_tanh(c[mt][nt][2] + b0) * gthi;
                o.y = gelu_tanh(c[mt][nt][3] + b1) * gthi;
                *(float2*)(g_y + (size_t)tshi * DDIM + col) = o;
            }
        }
    }
}

// g_c[t] = rna_tf32(y[t,slot0] + y[t,slot1]) — one rounding after the sum
__global__ void combine_kernel() {
    int i = blockIdx.x * blockDim.x + threadIdx.x;   // float4 index
    const int per = DDIM / 4;
    int t = i / per;
    int d = i - t * per;
    const float4* y = (const float4*)g_y;
    float4 u = y[(size_t)(2 * t) * per + d];
    float4 v = y[(size_t)(2 * t + 1) * per + d];
    float4 r;
    r.x = tf32r(u.x + v.x);
    r.y = tf32r(u.y + v.y);
    r.z = tf32r(u.z + v.z);
    r.w = tf32r(u.w + v.w);
    ((float4*)g_c)[i] = r;
}

// Output projection (tf32 tensor, cp.async 4-stage): out = g_c @ out_w + out_b
__global__ __launch_bounds__(256, 2)
void out_gemm_tf32(const float* __restrict__ ob, float* __restrict__ out) {
    extern __shared__ char smem[];
    unsigned sbase;
    asm("{ .reg .u64 t; cvta.to.shared.u64 t, %1; cvt.u32.u64 %0, t; }"
        : "=r"(sbase) : "l"(smem));

    int m0 = blockIdx.y * BM;
    int n0 = blockIdx.x * BN;

    int tid = threadIdx.x;
    int lane = tid & 31;
    int wid  = tid >> 5;
    int wm = wid >> 2, wn = wid & 3;
    int lq = lane >> 2, tg = lane & 3;

    int mA = tid >> 1;
    int kqA = (tid & 1) * 8;
    const float* asrc = g_c + (size_t)(m0 + mA) * DDIM + kqA;
    unsigned adst = sbase + (mA * ASTR + kqA) * 4;

    int kB = tid >> 4;
    int nB = (tid & 15) * 8;
    const float* bsrc = g_owr + (size_t)kB * DDIM + n0 + nB;
    unsigned bdst = sbase + NSTAGE * A_STAGE_BYTES + (kB * BSTR + nB) * 4;

#define ISSUE(st, k0)                                                             \
    do {                                                                          \
        cp16(adst + (st) * A_STAGE_BYTES,      asrc + (k0),          16);         \
        cp16(adst + (st) * A_STAGE_BYTES + 16, asrc + (k0) + 4,      16);         \
        cp16(bdst + (st) * B_STAGE_BYTES,      bsrc + (size_t)(k0) * DDIM,     16); \
        cp16(bdst + (st) * B_STAGE_BYTES + 16, bsrc + (size_t)(k0) * DDIM + 4, 16); \
        cp_commit();                                                              \
    } while (0)

    float c[4][4][4];
#pragma unroll
    for (int i = 0; i < 4; i++)
#pragma unroll
        for (int j = 0; j < 4; j++)
#pragma unroll
            for (int q = 0; q < 4; q++) c[i][j][q] = 0.f;

    ISSUE(0, 0); ISSUE(1, BK); ISSUE(2, 2 * BK);

    const int NK = DDIM / BK;
#pragma unroll 1
    for (int i = 0; i < NK; i++) {
        cp_wait2();
        __syncthreads();
        int st = i & 3;
        compute_stage((const unsigned (*)[ASTR])(smem + st * A_STAGE_BYTES),
                      (const unsigned (*)[BSTR])(smem + NSTAGE * A_STAGE_BYTES + st * B_STAGE_BYTES),
                      c, wm, wn, lq, tg);
        int nx = i + NSTAGE - 1;
        if (nx < NK) { ISSUE(nx & 3, nx * BK); }
        else         { cp_commit(); }
    }
#undef ISSUE

#pragma unroll
    for (int mt = 0; mt < 4; mt++) {
        int rlo = m0 + wm * 64 + mt * 16 + lq;
        int rhi = rlo + 8;
#pragma unroll
        for (int nt = 0; nt < 4; nt++) {
            int col = n0 + wn * 32 + nt * 8 + 2 * tg;
            float b0 = ob[col], b1 = ob[col + 1];
            float2 o;
            o.x = c[mt][nt][0] + b0;
            o.y = c[mt][nt][1] + b1;
            *(float2*)(out + (size_t)rlo * DDIM + col) = o;
            o.x = c[mt][nt][2] + b0;
            o.y = c[mt][nt][3] + b1;
            *(float2*)(out + (size_t)rhi * DDIM + col) = o;
        }
    }
}

extern "C" void kernel_launch(void* const* d_in, const int* in_sizes, int n_in,
                              void* d_out, int out_size) {
    const float* x  = (const float*)d_in[0];
    const float* rw = (const float*)d_in[1];
    const float* rb = (const float*)d_in[2];
    const float* ew = (const float*)d_in[3];
    const float* eb = (const float*)d_in[4];
    const float* ow = (const float*)d_in[5];
    const float* ob = (const float*)d_in[6];
    float* out = (float*)d_out;

    cudaFuncSetAttribute(expert_gemm_tf32,
                         cudaFuncAttributeMaxDynamicSharedMemorySize, SMEM_BYTES);
    cudaFuncSetAttribute(out_gemm_tf32,
                         cudaFuncAttributeMaxDynamicSharedMemorySize, SMEM_BYTES);

    float* ewr; cudaGetSymbolAddress((void**)&ewr, g_ewr);
    float* owr; cudaGetSymbolAddress((void**)&owr, g_owr);

    zero_cnt_kernel<<<1, 32>>>();
    router_kernel<<<T_TOK, 256>>>(x, rw, rb);

    int new4 = NEXP * HDIM * DDIM / 4;
    preround_kernel<<<(new4 + 255) / 256, 256>>>(ew, ewr, new4);
    int now4 = DDIM * DDIM / 4;
    preround_kernel<<<(now4 + 255) / 256, 256>>>(ow, owr, now4);

    dim3 g1(DDIM / BN, T_TOK / BM, NEXP);
    expert_gemm_tf32<<<g1, 256, SMEM_BYTES>>>(eb);

    combine_kernel<<<(T_TOK * DDIM / 4) / 256, 256>>>();

    dim3 g2(DDIM / BN, T_TOK / BM);
    out_gemm_tf32<<<g2, 256, SMEM_BYTES>>>(ob, out);
}